// round 10
// baseline (speedup 1.0000x reference)
#include <cuda_runtime.h>
#include <math.h>

#define BB 64
#define AA 8732
#define CC 81
#define GG 32
#define NEG_RATIO 3
#define IOU_THR 0.5f
#define TROWS 128
#define NBS 69          // streaming blocks per batch: ceil(8732/128)
#define NBM 69          // matching blocks per batch: ceil(8732/128)

// ---------------- device scratch (no allocs allowed) ----------------
__device__ float4             g_tloc[BB * AA];      // pre-scatter encodings (lab>0 rows only)
__device__ int                g_tlab[BB * AA];      // pre-scatter labels
__device__ unsigned long long g_bpp[BB * NBM * GG]; // per-block best-prior partials
__device__ float              g_raw[BB * AA];       // lse - conf0 per row
__device__ float4             g_bres[BB];           // {locsum, clspos, clsneg, numpos}
__device__ int                g_done;

__device__ __forceinline__ float smooth_l1(float d) {
    float ad = fabsf(d);
    return ad < 1.0f ? 0.5f * d * d : ad - 0.5f;
}

struct K1Smem {
    float gx1[GG], gy1[GG], gx2[GG], gy2[GG], garea[GG];
    float gcx[GG], gcy[GG], gw[GG], gh[GG];
    int   glab[GG];
    unsigned long long sbp[GG];
};

// ---------------- F1: fused conf-streaming (x<NBS) + matching (x>=NBS) ----------
__global__ void __launch_bounds__(128)
f1_fused(const float* __restrict__ conf,
         const float4* __restrict__ anchors,
         const float4* __restrict__ gt_boxes,
         const int*    __restrict__ gt_labels) {
    __shared__ __align__(16) float sx[TROWS * CC];  // 41472 B
    int b = blockIdx.y;
    int t = threadIdx.x;

    if (blockIdx.x >= NBS) {
        // ================= matching part (128 anchors/block) =================
        int bx = blockIdx.x - NBS;
        K1Smem* sm = reinterpret_cast<K1Smem*>(&sx[0]);

        if (bx == 0 && b == 0 && t == 0) g_done = 0;

        if (t < GG) {
            float4 g = gt_boxes[b * GG + t];
            float x1 = g.x - g.z * 0.5f, y1 = g.y - g.w * 0.5f;
            float x2 = g.x + g.z * 0.5f, y2 = g.y + g.w * 0.5f;
            sm->gx1[t] = x1; sm->gy1[t] = y1; sm->gx2[t] = x2; sm->gy2[t] = y2;
            sm->garea[t] = (x2 - x1) * (y2 - y1);
            sm->gcx[t] = g.x; sm->gcy[t] = g.y; sm->gw[t] = g.z; sm->gh[t] = g.w;
            sm->glab[t] = gt_labels[b * GG + t];
            sm->sbp[t] = 0xFFFFFFFFull;
        }
        __syncthreads();

        int a = bx * TROWS + t;
        bool valid = a < AA;

        float4 an = valid ? anchors[a] : make_float4(2.0f, 2.0f, 0.01f, 0.01f);
        float ax1 = an.x - an.z * 0.5f, ay1 = an.y - an.w * 0.5f;
        float ax2 = an.x + an.z * 0.5f, ay2 = an.y + an.w * 0.5f;
        float aarea = (ax2 - ax1) * (ay2 - ay1);

        int warpbase = bx * TROWS + (t & ~31);
        float best = -1.0f;
        int   bidx = 0;
#pragma unroll 4
        for (int g = 0; g < GG; g++) {
            float ltx = fmaxf(sm->gx1[g], ax1), lty = fmaxf(sm->gy1[g], ay1);
            float rbx = fminf(sm->gx2[g], ax2), rby = fminf(sm->gy2[g], ay2);
            float w = fmaxf(rbx - ltx, 0.0f), h = fmaxf(rby - lty, 0.0f);
            float inter = w * h;
            bool ov = valid && (inter > 0.0f);
            float iou = ov ? __fdividef(inter, sm->garea[g] + aarea - inter) : 0.0f;
            if (valid && iou > best) { best = iou; bidx = g; }

            if (__any_sync(0xffffffffu, ov)) {
                unsigned ib = ov ? __float_as_uint(iou) : 0u;
                unsigned mx = __reduce_max_sync(0xffffffffu, ib);
                unsigned ball = __ballot_sync(0xffffffffu, ib == mx);
                if ((t & 31) == 0) {
                    unsigned win_a = (unsigned)warpbase + (unsigned)(__ffs(ball) - 1);
                    unsigned long long key =
                        (((unsigned long long)mx) << 32) |
                        (unsigned long long)(0xFFFFFFFFu - win_a);
                    atomicMax(&sm->sbp[g], key);
                }
            }
        }

        if (valid) {
            size_t idx = (size_t)b * AA + a;
            if (best > IOU_THR) {
                float4 enc;
                enc.x = (sm->gcx[bidx] - an.x) / an.z;
                enc.y = (sm->gcy[bidx] - an.y) / an.w;
                enc.z = logf(sm->gw[bidx]) - logf(an.z);
                enc.w = logf(sm->gh[bidx]) - logf(an.w);
                g_tloc[idx] = enc;
                g_tlab[idx] = sm->glab[bidx];
            } else {
                g_tlab[idx] = 0;
            }
        }

        __syncthreads();
        if (t < GG)
            g_bpp[((size_t)b * NBM + bx) * GG + t] = sm->sbp[t];
        return;
    }

    // ============ conf streaming: stage tile, thread-per-row reduce ============
    int rowstart = blockIdx.x * TROWS;
    int nrows = min(TROWS, AA - rowstart);   // 128, tail 28 (%4==0)
    size_t growb = (size_t)b * AA + rowstart;

    // coalesced float4 staging (base 16B-aligned: growb*CC % 4 == 0)
    const float4* src = reinterpret_cast<const float4*>(conf + growb * CC);
    float4* dst = reinterpret_cast<float4*>(sx);
    int nv = nrows * CC / 4;
#pragma unroll 7
    for (int i = t; i < nv; i += 128)
        dst[i] = __ldcs(src + i);
    __syncthreads();

    if (t < nrows) {
        const float* row = sx + t * CC;
        float a0 = 0.f, a1 = 0.f, a2 = 0.f, a3 = 0.f;
#pragma unroll
        for (int c = 0; c < 80; c += 4) {
            a0 += __expf(row[c]);
            a1 += __expf(row[c + 1]);
            a2 += __expf(row[c + 2]);
            a3 += __expf(row[c + 3]);
        }
        a0 += __expf(row[80]);
        float esum = (a0 + a1) + (a2 + a3);
        g_raw[growb + t] = __logf(esum) - row[0];  // lse - conf0 (coalesced store)
    }
}

// ---------------- block-parallel descending bin search ----------------
__device__ __forceinline__ void find_bin_block(const int* h, int N, int P, int k,
                                               int* sres, int* swarp) {
    int t = threadIdx.x, lane = t & 31, w = t >> 5;
    int nt = N / P;
    int local = 0;
    if (t < nt)
        for (int j = 0; j < P; j++) local += h[t * P + j];
    int suf = local;
#pragma unroll
    for (int o = 1; o < 32; o <<= 1) {
        int x = __shfl_down_sync(0xffffffffu, suf, o);
        if (lane + o < 32) suf += x;
    }
    if (t < nt && lane == 0) swarp[w] = suf;
    __syncthreads();
    if (t < nt) {
        int nw = nt >> 5;
        int above = suf - local;
        for (int w2 = w + 1; w2 < nw; w2++) above += swarp[w2];
        if (above < k && k <= above + local) {
            int acc = above, bin = t * P;
            for (int j = P - 1; j >= 0; j--) {
                int c = h[t * P + j];
                if (k <= acc + c) { bin = t * P + j; break; }
                acc += c;
            }
            sres[0] = bin; sres[1] = acc;
        }
    }
    __syncthreads();
}

// ---------------- K4': in-smem scatter + positives + radix top-k + final --------
#define KV 9   // ceil(AA/1024)
#define NBMW 273  // ceil(AA/32) bitmap words

__global__ void __launch_bounds__(1024)
k4_final(const float* __restrict__ conf,
         const float4* __restrict__ locp,
         const float4* __restrict__ anchors,
         const float4* __restrict__ gt_boxes,
         const int*    __restrict__ gt_labels,
         float* __restrict__ out) {
    __shared__ int h1[256];
    __shared__ int h2[2048];
    __shared__ int h3[4096];
    __shared__ unsigned sbm[NBMW];          // claimed-anchor bitmap
    __shared__ unsigned claimed_aidx[GG];
    __shared__ int      claimed_lab[GG];
    __shared__ float4   claimed_enc[GG];
    __shared__ unsigned long long skey[GG];
    __shared__ int swarp[32];
    __shared__ int sres[2];
    __shared__ float sfA[32], sfB[32], sfC[32];
    __shared__ int siA[33], siB[32];
    __shared__ int slast;
    int b = blockIdx.x;
    int t = threadIdx.x;
    int lane = t & 31, w = t >> 5;

    // ---- prefetch raw + pre-scatter labels (both final from f1) ----
    float rawv[KV];
    int lab[KV];
#pragma unroll
    for (int it = 0; it < KV; it++) {
        int i = t + it * 1024;
        if (i < AA) {
            rawv[it] = g_raw[(size_t)b * AA + i];
            lab[it]  = g_tlab[(size_t)b * AA + i];
        } else { rawv[it] = 0.0f; lab[it] = 0; }
    }
    for (int i = t; i < 256;  i += 1024) h1[i] = 0;
    for (int i = t; i < 2048; i += 1024) h2[i] = 0;
    for (int i = t; i < 4096; i += 1024) h3[i] = 0;
    for (int i = t; i < NBMW; i += 1024) sbm[i] = 0u;

    // ---- parallel best-prior partial reduce (warp w = gt w) ----
    {
        unsigned long long key = 0xFFFFFFFFull;
        for (int blk = lane; blk < NBM; blk += 32) {
            unsigned long long x = g_bpp[((size_t)b * NBM + blk) * GG + w];
            if (x > key) key = x;
        }
#pragma unroll
        for (int o = 16; o; o >>= 1) {
            unsigned long long x = __shfl_xor_sync(0xffffffffu, key, o);
            if (x > key) key = x;
        }
        if (lane == 0) skey[w] = key;
    }
    __syncthreads();

    // ---- warp 0: duplicate resolution, claimed table + bitmap (smem only) ----
    if (t < GG) {
        unsigned aidx = 0xFFFFFFFFu - (unsigned)(skey[t] & 0xFFFFFFFFull);
        claimed_aidx[t] = aidx;
        __syncwarp();
        bool win = true;
        for (int g2 = t + 1; g2 < GG; g2++)
            if (claimed_aidx[g2] == aidx) win = false;  // later gt wins duplicates
        __syncwarp();
        if (win) {
            float4 gt = gt_boxes[b * GG + t];
            float4 an = anchors[aidx];
            float4 enc;
            enc.x = (gt.x - an.x) / an.z;
            enc.y = (gt.y - an.y) / an.w;
            enc.z = logf(gt.z) - logf(an.z);
            enc.w = logf(gt.w) - logf(an.w);
            claimed_enc[t] = enc;
            claimed_lab[t] = gt_labels[b * GG + t];
            atomicOr(&sbm[aidx >> 5], 1u << (aidx & 31));
        } else {
            claimed_aidx[t] = 0xFFFFFFFFu;  // exclude losers from scans
        }
    }
    __syncthreads();

    // ---- per-row: apply overrides, count positives, build mining values ----
    unsigned v[KV];
    float cp = 0.0f, ls = 0.0f;
    int np = 0;
#pragma unroll
    for (int it = 0; it < KV; it++) {
        int i = t + it * 1024;
        if (i < AA) {
            bool claimed = (sbm[i >> 5] >> (i & 31)) & 1u;
            int l = lab[it];
            float4 tl;
            bool have_tl = false;
            if (claimed) {
                for (int g = 0; g < GG; g++) {
                    if (claimed_aidx[g] == (unsigned)i) {
                        l = claimed_lab[g];
                        tl = claimed_enc[g];
                        have_tl = true;
                        break;
                    }
                }
            }
            bool pos = l > 0;
            if (pos) {
                np++;
                size_t row = (size_t)b * AA + i;
                if (!have_tl) tl = g_tloc[row];
                float c0   = conf[row * CC];
                float clab = conf[row * CC + l];
                cp += rawv[it] + c0 - clab;   // = lse - conf[lab]
                float4 lp = locp[row];
                ls += smooth_l1(lp.x - tl.x) + smooth_l1(lp.y - tl.y) +
                      smooth_l1(lp.z - tl.z) + smooth_l1(lp.w - tl.w);
                v[it] = 0u;                   // positives excluded from mining
            } else {
                v[it] = __float_as_uint(rawv[it]);
            }
        } else v[it] = 0u;
    }
    // np total
    {
        int x = np;
#pragma unroll
        for (int o = 16; o; o >>= 1) x += __shfl_xor_sync(0xffffffffu, x, o);
        if (lane == 0) siA[w] = x;
    }
    __syncthreads();
    if (t < 32) {
        int x = siA[t];
#pragma unroll
        for (int o = 16; o; o >>= 1) x += __shfl_xor_sync(0xffffffffu, x, o);
        if (t == 0) siA[32] = x;
    }
    __syncthreads();
    int np_total = siA[32];
    int k = min(NEG_RATIO * np_total, AA - 1);

    // ---- 3-round radix select ----
    float s = 0.0f;
    int cgt = 0;
    float vk = 0.0f;
    if (k > 0) {
#pragma unroll
        for (int it = 0; it < KV; it++) {
            int bin = (int)(v[it] >> 23);
            unsigned m = __match_any_sync(0xffffffffu, bin);
            if (lane == __ffs(m) - 1) atomicAdd(&h1[bin], __popc(m));
        }
        __syncthreads();
        find_bin_block(h1, 256, 1, k, sres, swarp);
        int E = sres[0];
        int k2 = k - sres[1];

#pragma unroll
        for (int it = 0; it < KV; it++) {
            if ((int)(v[it] >> 23) == E)
                atomicAdd(&h2[(v[it] >> 12) & 2047u], 1);
        }
        __syncthreads();
        find_bin_block(h2, 2048, 2, k2, sres, swarp);
        unsigned P = ((unsigned)E << 11) | (unsigned)sres[0];
        int k3 = k2 - sres[1];

#pragma unroll
        for (int it = 0; it < KV; it++) {
            if ((v[it] >> 12) == P)
                atomicAdd(&h3[v[it] & 4095u], 1);
        }
        __syncthreads();
        find_bin_block(h3, 4096, 4, k3, sres, swarp);
        unsigned lo = (P << 12) | (unsigned)sres[0];  // exact k-th largest bits
        vk = __uint_as_float(lo);

#pragma unroll
        for (int it = 0; it < KV; it++) {
            if (v[it] > lo) { s += __uint_as_float(v[it]); cgt++; }
        }
    }

    // ---- combined block reduce ----
#pragma unroll
    for (int o = 16; o; o >>= 1) {
        cp  += __shfl_xor_sync(0xffffffffu, cp, o);
        ls  += __shfl_xor_sync(0xffffffffu, ls, o);
        s   += __shfl_xor_sync(0xffffffffu, s, o);
        cgt += __shfl_xor_sync(0xffffffffu, cgt, o);
    }
    if (lane == 0) { sfA[w] = cp; sfB[w] = ls; sfC[w] = s; siB[w] = cgt; }
    __syncthreads();
    if (t == 0) {
        float cpt = 0.f, lst = 0.f, st = 0.f;
        int cgtt = 0;
#pragma unroll
        for (int w2 = 0; w2 < 32; w2++) {
            cpt += sfA[w2]; lst += sfB[w2]; st += sfC[w2]; cgtt += siB[w2];
        }
        float result = (k > 0) ? (st + (float)(k - cgtt) * vk) : 0.0f;
        g_bres[b] = make_float4(lst, cpt, result, (float)np_total);
        __threadfence();
        int done = atomicAdd(&g_done, 1);
        slast = (done == BB - 1) ? 1 : 0;
    }
    __syncthreads();

    // ---- last block: parallel final combine ----
    if (slast && w < 2) {  // threads 0..63, one per batch
        float4 r = g_bres[t];
        float loc = r.x, cpos = r.y, cn = r.z;
        int npb = (int)r.w;
        int nsb = npb + min(NEG_RATIO * npb, AA - 1);
#pragma unroll
        for (int o = 16; o; o >>= 1) {
            loc  += __shfl_xor_sync(0xffffffffu, loc, o);
            cpos += __shfl_xor_sync(0xffffffffu, cpos, o);
            cn   += __shfl_xor_sync(0xffffffffu, cn, o);
            npb  += __shfl_xor_sync(0xffffffffu, npb, o);
            nsb  += __shfl_xor_sync(0xffffffffu, nsb, o);
        }
        if (lane == 0) {
            sfA[w] = loc; sfB[w] = cpos; sfC[w] = cn;
            siA[w] = npb; siB[w] = nsb;
        }
        __syncwarp();
        if (t == 0) {
            float loct = sfA[0] + sfA[1];
            float cpt  = sfB[0] + sfB[1];
            float cnt  = sfC[0] + sfC[1];
            long long npt = siA[0] + siA[1];
            long long nst = siB[0] + siB[1];
            float cls = cpt + cnt +
                        (float)((long long)BB * AA - nst) * logf((float)CC);
            out[0] = (loct + cls) / (float)npt;
        }
    }
}

// ---------------- launch ----------------
extern "C" void kernel_launch(void* const* d_in, const int* in_sizes, int n_in,
                              void* d_out, int out_size) {
    const float4* loc_pred  = (const float4*)d_in[0];
    const float*  conf_pred = (const float*)d_in[1];
    const float4* anchors   = (const float4*)d_in[2];
    const float4* gt_boxes  = (const float4*)d_in[3];
    const int*    gt_labels = (const int*)d_in[4];
    float* out = (float*)d_out;

    dim3 gf(NBS + NBM, BB);   // 138 x 64 blocks of 128 threads
    f1_fused<<<gf, 128>>>(conf_pred, anchors, gt_boxes, gt_labels);

    k4_final<<<BB, 1024>>>(conf_pred, loc_pred, anchors, gt_boxes, gt_labels, out);
}

// round 11
// speedup vs baseline: 1.2622x; 1.2622x over previous
#include <cuda_runtime.h>
#include <math.h>

#define BB 64
#define AA 8732
#define CC 81
#define GG 32
#define NEG_RATIO 3
#define IOU_THR 0.5f
#define TROWS 128
#define NBS 69          // streaming blocks per batch: ceil(8732/128)
#define NBM 35          // matching blocks per batch: ceil(8732/256)

// ---------------- device scratch (no allocs allowed) ----------------
__device__ float4             g_tloc[BB * AA];      // pre-scatter encodings (lab>0 rows only)
__device__ int                g_tlab[BB * AA];      // pre-scatter labels
__device__ unsigned long long g_bpp[BB * NBM * GG]; // per-block best-prior partials
__device__ float              g_raw[BB * AA];       // lse - conf0 per row
__device__ float4             g_bres[BB];           // {locsum, clspos, clsneg, numpos}
__device__ int                g_done;

__device__ __forceinline__ float smooth_l1(float d) {
    float ad = fabsf(d);
    return ad < 1.0f ? 0.5f * d * d : ad - 0.5f;
}

struct K1Smem {
    float gx1[GG], gy1[GG], gx2[GG], gy2[GG], garea[GG];
    float gcx[GG], gcy[GG], gw[GG], gh[GG];
    int   glab[GG];
    unsigned long long sbp[GG];
};

// ---------------- F1: fused conf-streaming (x<NBS) + matching (x>=NBS) ----------
__global__ void __launch_bounds__(256)
f1_fused(const float* __restrict__ conf,
         const float4* __restrict__ anchors,
         const float4* __restrict__ gt_boxes,
         const int*    __restrict__ gt_labels) {
    // 8 warps x 2 buffers x 324 floats = 20736 B
    __shared__ __align__(16) float sx[8 * 2 * 324];
    int b = blockIdx.y;
    int t = threadIdx.x;
    int w = t >> 5;
    int lane = t & 31;

    if (blockIdx.x >= NBS) {
        // ================= matching part (256 anchors/block) =================
        int bx = blockIdx.x - NBS;
        K1Smem* sm = reinterpret_cast<K1Smem*>(&sx[0]);

        if (bx == 0 && b == 0 && t == 0) g_done = 0;

        if (t < GG) {
            float4 g = gt_boxes[b * GG + t];
            float x1 = g.x - g.z * 0.5f, y1 = g.y - g.w * 0.5f;
            float x2 = g.x + g.z * 0.5f, y2 = g.y + g.w * 0.5f;
            sm->gx1[t] = x1; sm->gy1[t] = y1; sm->gx2[t] = x2; sm->gy2[t] = y2;
            sm->garea[t] = (x2 - x1) * (y2 - y1);
            sm->gcx[t] = g.x; sm->gcy[t] = g.y; sm->gw[t] = g.z; sm->gh[t] = g.w;
            sm->glab[t] = gt_labels[b * GG + t];
            sm->sbp[t] = 0xFFFFFFFFull;
        }
        __syncthreads();

        int a = bx * 256 + t;
        bool valid = a < AA;

        float4 an = valid ? anchors[a] : make_float4(2.0f, 2.0f, 0.01f, 0.01f);
        float ax1 = an.x - an.z * 0.5f, ay1 = an.y - an.w * 0.5f;
        float ax2 = an.x + an.z * 0.5f, ay2 = an.y + an.w * 0.5f;
        float aarea = (ax2 - ax1) * (ay2 - ay1);

        int warpbase = bx * 256 + (t & ~31);
        float best = -1.0f;
        int   bidx = 0;
#pragma unroll 4
        for (int g = 0; g < GG; g++) {
            float ltx = fmaxf(sm->gx1[g], ax1), lty = fmaxf(sm->gy1[g], ay1);
            float rbx = fminf(sm->gx2[g], ax2), rby = fminf(sm->gy2[g], ay2);
            float ww = fmaxf(rbx - ltx, 0.0f), hh = fmaxf(rby - lty, 0.0f);
            float inter = ww * hh;
            bool ov = valid && (inter > 0.0f);
            float iou = ov ? __fdividef(inter, sm->garea[g] + aarea - inter) : 0.0f;
            if (valid && iou > best) { best = iou; bidx = g; }

            if (__any_sync(0xffffffffu, ov)) {
                unsigned ib = ov ? __float_as_uint(iou) : 0u;
                unsigned mx = __reduce_max_sync(0xffffffffu, ib);
                unsigned ball = __ballot_sync(0xffffffffu, ib == mx);
                if (lane == 0) {
                    unsigned win_a = (unsigned)warpbase + (unsigned)(__ffs(ball) - 1);
                    unsigned long long key =
                        (((unsigned long long)mx) << 32) |
                        (unsigned long long)(0xFFFFFFFFu - win_a);
                    atomicMax(&sm->sbp[g], key);
                }
            }
        }

        if (valid) {
            size_t idx = (size_t)b * AA + a;
            if (best > IOU_THR) {
                float4 enc;
                enc.x = (sm->gcx[bidx] - an.x) / an.z;
                enc.y = (sm->gcy[bidx] - an.y) / an.w;
                enc.z = logf(sm->gw[bidx]) - logf(an.z);
                enc.w = logf(sm->gh[bidx]) - logf(an.w);
                g_tloc[idx] = enc;
                g_tlab[idx] = sm->glab[bidx];
            } else {
                g_tlab[idx] = 0;
            }
        }

        __syncthreads();
        if (t < GG)
            g_bpp[((size_t)b * NBM + bx) * GG + t] = sm->sbp[t];
        return;
    }

    // ============ conf streaming: warp-autonomous reg-pipelined groups ============
    int rowstart = blockIdx.x * TROWS;
    int nrows = min(TROWS, AA - rowstart);   // 128, tail 28 (%4==0)
    size_t growb = (size_t)b * AA + rowstart;
    const float4* gsrc = reinterpret_cast<const float4*>(conf + growb * CC);

    int base = w * 16;                        // warp's first row in tile
    int ng = (base < nrows) ? min(4, (nrows - base) >> 2) : 0;  // 4-row groups
    const float4* wsrc = gsrc + w * 324;      // 16 rows * 81 floats / 4
    float* ws = sx + w * 648;                 // warp slice: 2 x 324 floats

    float4 ra, rb4, rc;
    auto ldg = [&](int g) {
        const float4* p = wsrc + g * 81;
        ra  = __ldcs(p + lane);
        rb4 = __ldcs(p + lane + 32);
        if (lane < 17) rc = __ldcs(p + lane + 64);
    };
    auto sts = [&](int g) {
        float4* d = reinterpret_cast<float4*>(ws + (g & 1) * 324);
        d[lane] = ra;
        d[lane + 32] = rb4;
        if (lane < 17) d[lane + 64] = rc;
    };

    if (ng > 0) { ldg(0); sts(0); }
    __syncwarp();

    for (int g = 0; g < ng; g++) {
        if (g + 1 < ng) ldg(g + 1);          // next group's LDG under this compute

        const float* buf = ws + (g & 1) * 324;
        float e[4];
#pragma unroll
        for (int r = 0; r < 4; r++) {
            const float* row = buf + r * CC;
            float tv = __expf(row[lane]) + __expf(row[32 + lane]);
            if (lane < 17) tv += __expf(row[64 + lane]);
            e[r] = tv;
        }
#pragma unroll
        for (int o = 16; o; o >>= 1) {
#pragma unroll
            for (int r = 0; r < 4; r++)
                e[r] += __shfl_xor_sync(0xffffffffu, e[r], o);
        }
        if (lane == 0) {
            size_t rowb = growb + base + g * 4;
            float4 res;
            res.x = __logf(e[0]) - buf[0 * CC];
            res.y = __logf(e[1]) - buf[1 * CC];
            res.z = __logf(e[2]) - buf[2 * CC];
            res.w = __logf(e[3]) - buf[3 * CC];
            *reinterpret_cast<float4*>(g_raw + rowb) = res;  // raw = lse - conf0
        }
        __syncwarp();
        if (g + 1 < ng) { sts(g + 1); __syncwarp(); }
    }
}

// ---------------- block-parallel descending bin search ----------------
__device__ __forceinline__ void find_bin_block(const int* h, int N, int P, int k,
                                               int* sres, int* swarp) {
    int t = threadIdx.x, lane = t & 31, w = t >> 5;
    int nt = N / P;
    int local = 0;
    if (t < nt)
        for (int j = 0; j < P; j++) local += h[t * P + j];
    int suf = local;
#pragma unroll
    for (int o = 1; o < 32; o <<= 1) {
        int x = __shfl_down_sync(0xffffffffu, suf, o);
        if (lane + o < 32) suf += x;
    }
    if (t < nt && lane == 0) swarp[w] = suf;
    __syncthreads();
    if (t < nt) {
        int nw = nt >> 5;
        int above = suf - local;
        for (int w2 = w + 1; w2 < nw; w2++) above += swarp[w2];
        if (above < k && k <= above + local) {
            int acc = above, bin = t * P;
            for (int j = P - 1; j >= 0; j--) {
                int c = h[t * P + j];
                if (k <= acc + c) { bin = t * P + j; break; }
                acc += c;
            }
            sres[0] = bin; sres[1] = acc;
        }
    }
    __syncthreads();
}

// ---------------- K4': in-smem scatter + positives + radix top-k + final --------
#define KV 9      // ceil(AA/1024)
#define NBMW 273  // ceil(AA/32) bitmap words

__global__ void __launch_bounds__(1024)
k4_final(const float* __restrict__ conf,
         const float4* __restrict__ locp,
         const float4* __restrict__ anchors,
         const float4* __restrict__ gt_boxes,
         const int*    __restrict__ gt_labels,
         float* __restrict__ out) {
    __shared__ int h1[256];
    __shared__ int h2[2048];
    __shared__ int h3[4096];
    __shared__ unsigned sbm[NBMW];
    __shared__ unsigned claimed_aidx[GG];
    __shared__ int      claimed_lab[GG];
    __shared__ float4   claimed_enc[GG];
    __shared__ unsigned long long skey[GG];
    __shared__ int swarp[32];
    __shared__ int sres[2];
    __shared__ float sfA[32], sfB[32], sfC[32];
    __shared__ int siA[33], siB[32];
    __shared__ int slast;
    int b = blockIdx.x;
    int t = threadIdx.x;
    int lane = t & 31, w = t >> 5;

    // ---- prefetch raw + pre-scatter labels ----
    float rawv[KV];
    int lab[KV];
#pragma unroll
    for (int it = 0; it < KV; it++) {
        int i = t + it * 1024;
        if (i < AA) {
            rawv[it] = g_raw[(size_t)b * AA + i];
            lab[it]  = g_tlab[(size_t)b * AA + i];
        } else { rawv[it] = 0.0f; lab[it] = 0; }
    }
    for (int i = t; i < 256;  i += 1024) h1[i] = 0;
    for (int i = t; i < 2048; i += 1024) h2[i] = 0;
    for (int i = t; i < 4096; i += 1024) h3[i] = 0;
    for (int i = t; i < NBMW; i += 1024) sbm[i] = 0u;

    // ---- parallel best-prior partial reduce (warp w = gt w) ----
    {
        unsigned long long key = 0xFFFFFFFFull;
        for (int blk = lane; blk < NBM; blk += 32) {
            unsigned long long x = g_bpp[((size_t)b * NBM + blk) * GG + w];
            if (x > key) key = x;
        }
#pragma unroll
        for (int o = 16; o; o >>= 1) {
            unsigned long long x = __shfl_xor_sync(0xffffffffu, key, o);
            if (x > key) key = x;
        }
        if (lane == 0) skey[w] = key;
    }
    __syncthreads();

    // ---- warp 0: duplicate resolution, claimed table + bitmap (smem only) ----
    if (t < GG) {
        unsigned aidx = 0xFFFFFFFFu - (unsigned)(skey[t] & 0xFFFFFFFFull);
        claimed_aidx[t] = aidx;
        __syncwarp();
        bool win = true;
        for (int g2 = t + 1; g2 < GG; g2++)
            if (claimed_aidx[g2] == aidx) win = false;  // later gt wins duplicates
        __syncwarp();
        if (win) {
            float4 gt = gt_boxes[b * GG + t];
            float4 an = anchors[aidx];
            float4 enc;
            enc.x = (gt.x - an.x) / an.z;
            enc.y = (gt.y - an.y) / an.w;
            enc.z = logf(gt.z) - logf(an.z);
            enc.w = logf(gt.w) - logf(an.w);
            claimed_enc[t] = enc;
            claimed_lab[t] = gt_labels[b * GG + t];
            atomicOr(&sbm[aidx >> 5], 1u << (aidx & 31));
        } else {
            claimed_aidx[t] = 0xFFFFFFFFu;
        }
    }
    __syncthreads();

    // ---- per-row: apply overrides, count positives, build mining values ----
    unsigned v[KV];
    float cp = 0.0f, ls = 0.0f;
    int np = 0;
#pragma unroll
    for (int it = 0; it < KV; it++) {
        int i = t + it * 1024;
        if (i < AA) {
            bool claimed = (sbm[i >> 5] >> (i & 31)) & 1u;
            int l = lab[it];
            float4 tl;
            bool have_tl = false;
            if (claimed) {
                for (int g = 0; g < GG; g++) {
                    if (claimed_aidx[g] == (unsigned)i) {
                        l = claimed_lab[g];
                        tl = claimed_enc[g];
                        have_tl = true;
                        break;
                    }
                }
            }
            bool pos = l > 0;
            if (pos) {
                np++;
                size_t row = (size_t)b * AA + i;
                if (!have_tl) tl = g_tloc[row];
                float c0   = conf[row * CC];
                float clab = conf[row * CC + l];
                cp += rawv[it] + c0 - clab;   // = lse - conf[lab]
                float4 lp = locp[row];
                ls += smooth_l1(lp.x - tl.x) + smooth_l1(lp.y - tl.y) +
                      smooth_l1(lp.z - tl.z) + smooth_l1(lp.w - tl.w);
                v[it] = 0u;
            } else {
                v[it] = __float_as_uint(rawv[it]);
            }
        } else v[it] = 0u;
    }
    {
        int x = np;
#pragma unroll
        for (int o = 16; o; o >>= 1) x += __shfl_xor_sync(0xffffffffu, x, o);
        if (lane == 0) siA[w] = x;
    }
    __syncthreads();
    if (t < 32) {
        int x = siA[t];
#pragma unroll
        for (int o = 16; o; o >>= 1) x += __shfl_xor_sync(0xffffffffu, x, o);
        if (t == 0) siA[32] = x;
    }
    __syncthreads();
    int np_total = siA[32];
    int k = min(NEG_RATIO * np_total, AA - 1);

    // ---- 3-round radix select ----
    float s = 0.0f;
    int cgt = 0;
    float vk = 0.0f;
    if (k > 0) {
#pragma unroll
        for (int it = 0; it < KV; it++) {
            int bin = (int)(v[it] >> 23);
            unsigned m = __match_any_sync(0xffffffffu, bin);
            if (lane == __ffs(m) - 1) atomicAdd(&h1[bin], __popc(m));
        }
        __syncthreads();
        find_bin_block(h1, 256, 1, k, sres, swarp);
        int E = sres[0];
        int k2 = k - sres[1];

#pragma unroll
        for (int it = 0; it < KV; it++) {
            if ((int)(v[it] >> 23) == E)
                atomicAdd(&h2[(v[it] >> 12) & 2047u], 1);
        }
        __syncthreads();
        find_bin_block(h2, 2048, 2, k2, sres, swarp);
        unsigned P = ((unsigned)E << 11) | (unsigned)sres[0];
        int k3 = k2 - sres[1];

#pragma unroll
        for (int it = 0; it < KV; it++) {
            if ((v[it] >> 12) == P)
                atomicAdd(&h3[v[it] & 4095u], 1);
        }
        __syncthreads();
        find_bin_block(h3, 4096, 4, k3, sres, swarp);
        unsigned lo = (P << 12) | (unsigned)sres[0];  // exact k-th largest bits
        vk = __uint_as_float(lo);

#pragma unroll
        for (int it = 0; it < KV; it++) {
            if (v[it] > lo) { s += __uint_as_float(v[it]); cgt++; }
        }
    }

    // ---- combined block reduce ----
#pragma unroll
    for (int o = 16; o; o >>= 1) {
        cp  += __shfl_xor_sync(0xffffffffu, cp, o);
        ls  += __shfl_xor_sync(0xffffffffu, ls, o);
        s   += __shfl_xor_sync(0xffffffffu, s, o);
        cgt += __shfl_xor_sync(0xffffffffu, cgt, o);
    }
    if (lane == 0) { sfA[w] = cp; sfB[w] = ls; sfC[w] = s; siB[w] = cgt; }
    __syncthreads();
    if (t == 0) {
        float cpt = 0.f, lst = 0.f, st = 0.f;
        int cgtt = 0;
#pragma unroll
        for (int w2 = 0; w2 < 32; w2++) {
            cpt += sfA[w2]; lst += sfB[w2]; st += sfC[w2]; cgtt += siB[w2];
        }
        float result = (k > 0) ? (st + (float)(k - cgtt) * vk) : 0.0f;
        g_bres[b] = make_float4(lst, cpt, result, (float)np_total);
        __threadfence();
        int done = atomicAdd(&g_done, 1);
        slast = (done == BB - 1) ? 1 : 0;
    }
    __syncthreads();

    // ---- last block: parallel final combine ----
    if (slast && w < 2) {  // threads 0..63, one per batch
        float4 r = g_bres[t];
        float loc = r.x, cpos = r.y, cn = r.z;
        int npb = (int)r.w;
        int nsb = npb + min(NEG_RATIO * npb, AA - 1);
#pragma unroll
        for (int o = 16; o; o >>= 1) {
            loc  += __shfl_xor_sync(0xffffffffu, loc, o);
            cpos += __shfl_xor_sync(0xffffffffu, cpos, o);
            cn   += __shfl_xor_sync(0xffffffffu, cn, o);
            npb  += __shfl_xor_sync(0xffffffffu, npb, o);
            nsb  += __shfl_xor_sync(0xffffffffu, nsb, o);
        }
        if (lane == 0) {
            sfA[w] = loc; sfB[w] = cpos; sfC[w] = cn;
            siA[w] = npb; siB[w] = nsb;
        }
        __syncwarp();
        if (t == 0) {
            float loct = sfA[0] + sfA[1];
            float cpt  = sfB[0] + sfB[1];
            float cnt  = sfC[0] + sfC[1];
            long long npt = siA[0] + siA[1];
            long long nst = siB[0] + siB[1];
            float cls = cpt + cnt +
                        (float)((long long)BB * AA - nst) * logf((float)CC);
            out[0] = (loct + cls) / (float)npt;
        }
    }
}

// ---------------- launch ----------------
extern "C" void kernel_launch(void* const* d_in, const int* in_sizes, int n_in,
                              void* d_out, int out_size) {
    const float4* loc_pred  = (const float4*)d_in[0];
    const float*  conf_pred = (const float*)d_in[1];
    const float4* anchors   = (const float4*)d_in[2];
    const float4* gt_boxes  = (const float4*)d_in[3];
    const int*    gt_labels = (const int*)d_in[4];
    float* out = (float*)d_out;

    dim3 gf(NBS + NBM, BB);   // 104 x 64 blocks of 256 threads
    f1_fused<<<gf, 256>>>(conf_pred, anchors, gt_boxes, gt_labels);

    k4_final<<<BB, 1024>>>(conf_pred, loc_pred, anchors, gt_boxes, gt_labels, out);
}